// round 10
// baseline (speedup 1.0000x reference)
#include <cuda_runtime.h>
#include <cstdint>

#define H      512
#define EPB    8
#define MAXROWS 100352   // multiple of 128, >= NUM_NODES

// ---------------- scratch: tf32-converted operands ----------------
__device__ unsigned int g_Bt[H * H];            // Bt[n][k] = tf32(lw[k][n])
__device__ unsigned int g_At[MAXROWS * H];      // At[m][k] = tf32(emb[m][k])

__device__ __forceinline__ unsigned int f2tf32(float f) {
    unsigned int u;
    asm("cvt.rna.tf32.f32 %0, %1;" : "=r"(u) : "f"(f));
    return u;
}
__device__ __forceinline__ uint32_t smem_u32(const void* p) {
    uint32_t a;
    asm("{ .reg .u64 t; cvta.to.shared.u64 t, %1; cvt.u32.u64 %0, t; }" : "=r"(a) : "l"(p));
    return a;
}
__device__ __forceinline__ void cp_async16(void* sptr, const void* gptr) {
    asm volatile("cp.async.cg.shared.global [%0], [%1], 16;"
                 :: "r"(smem_u32(sptr)), "l"(gptr));
}
__device__ __forceinline__ void red4(float* p, float4 v) {
    asm volatile("red.global.add.v4.f32 [%0], {%1, %2, %3, %4};"
                 :: "l"(p), "f"(v.x), "f"(v.y), "f"(v.z), "f"(v.w) : "memory");
}
__device__ __forceinline__ void red2(float* p, float a, float b) {
    asm volatile("red.global.add.v2.f32 [%0], {%1, %2};"
                 :: "l"(p), "f"(a), "f"(b) : "memory");
}

// ---------------- transpose 512x512 + tf32 round ----------------
__global__ void transpose512(const float* __restrict__ lw) {
    __shared__ float t[32][33];
    const int bx = blockIdx.x * 32, by = blockIdx.y * 32;
#pragma unroll
    for (int j = 0; j < 4; j++)
        t[threadIdx.y + 8 * j][threadIdx.x] =
            lw[(by + threadIdx.y + 8 * j) * H + bx + threadIdx.x];
    __syncthreads();
#pragma unroll
    for (int j = 0; j < 4; j++)
        g_Bt[(bx + threadIdx.y + 8 * j) * H + by + threadIdx.x] =
            f2tf32(t[threadIdx.x][threadIdx.y + 8 * j]);
}

// ---------------- pre-convert emb -> tf32 ----------------
__global__ void cvtA_kernel(const float* __restrict__ emb, int n4) {
    const int i = blockIdx.x * 256 + threadIdx.x;
    if (i < n4) {
        float4 v = ((const float4*)emb)[i];
        uint4 u;
        u.x = f2tf32(v.x); u.y = f2tf32(v.y);
        u.z = f2tf32(v.z); u.w = f2tf32(v.w);
        ((uint4*)g_At)[i] = u;
    }
}

// ---------------- fused heterogeneous kernel ----------------
// GEMM: 128x128 tile, warp tile 32x64, cp.async 3-stage pipeline, both
// operands pre-converted tf32. Edge: R6 coalesced quad-per-base.
// out must be pre-zeroed.
#define BK      16
#define LDS_S   20
#define STG_U   (2 * 128 * LDS_S)      // uints per stage (A then B)
#define A_OFF   0
#define B_OFF   (128 * LDS_S)
#define SMEM_DYN (3 * STG_U * 4)       // 61440 bytes

__global__ __launch_bounds__(256)
void fused_kernel(const float* __restrict__ A, const float* __restrict__ bias,
                  const void* __restrict__ srcv, const void* __restrict__ dstv,
                  const void* __restrict__ etv, const float* __restrict__ norm,
                  const float* __restrict__ wt,
                  float* __restrict__ out, int M, int E, int GB, int TOT)
{
    const int tid  = threadIdx.x;
    const int wid  = tid >> 5;
    const int lane = tid & 31;

    const long long bid = blockIdx.x;
    const long long g   = bid * GB / TOT;
    const bool is_gemm  = ((bid + 1) * GB / TOT) > g;

    if (is_gemm) {
        // ================= GEMM part =================
        extern __shared__ unsigned int smemu[];

        const int tile = (int)g;
        const int l4  = lane >> 2;
        const int lm  = lane & 3;
        const int bm  = (tile >> 2) * 128;
        const int bn  = (tile & 3) * 128;
        const int wm0 = (wid & 3) * 32;
        const int wn0 = (wid >> 2) * 64;

        float acc[2][8][4];
#pragma unroll
        for (int i = 0; i < 2; i++)
#pragma unroll
            for (int j = 0; j < 8; j++)
#pragma unroll
                for (int q = 0; q < 4; q++) acc[i][j][q] = 0.f;

        // cp.async mapping: 2 A-rows + 2 B-rows per thread
        const int r0 = tid >> 2;            // 0..63
        const int r1 = (tid + 256) >> 2;    // 64..127
        const int kq = tid & 3;

        auto issue_stage = [&](int kt, int s) {
            unsigned int* As = smemu + s * STG_U + A_OFF;
            unsigned int* Bs = smemu + s * STG_U + B_OFF;
            cp_async16(&As[r0 * LDS_S + kq * 4],
                       g_At + (size_t)(bm + r0) * H + kt + kq * 4);
            cp_async16(&As[r1 * LDS_S + kq * 4],
                       g_At + (size_t)(bm + r1) * H + kt + kq * 4);
            cp_async16(&Bs[r0 * LDS_S + kq * 4],
                       g_Bt + (size_t)(bn + r0) * H + kt + kq * 4);
            cp_async16(&Bs[r1 * LDS_S + kq * 4],
                       g_Bt + (size_t)(bn + r1) * H + kt + kq * 4);
        };

        const int NK = H / BK;   // 32
        issue_stage(0, 0);
        asm volatile("cp.async.commit_group;");
        issue_stage(BK, 1);
        asm volatile("cp.async.commit_group;");

        for (int kt = 0; kt < NK; kt++) {
            asm volatile("cp.async.wait_group 1;");
            __syncthreads();

            if (kt + 2 < NK) issue_stage((kt + 2) * BK, (kt + 2) % 3);
            asm volatile("cp.async.commit_group;");

            const unsigned int* As = smemu + (kt % 3) * STG_U + A_OFF;
            const unsigned int* Bs = smemu + (kt % 3) * STG_U + B_OFF;
#pragma unroll
            for (int ks = 0; ks < 2; ks++) {
                const int k8 = ks * 8;
                unsigned int af[2][4];
#pragma unroll
                for (int mt = 0; mt < 2; mt++) {
                    const int rm = wm0 + mt * 16 + l4;
                    af[mt][0] = As[rm * LDS_S + k8 + lm];
                    af[mt][1] = As[(rm + 8) * LDS_S + k8 + lm];
                    af[mt][2] = As[rm * LDS_S + k8 + lm + 4];
                    af[mt][3] = As[(rm + 8) * LDS_S + k8 + lm + 4];
                }
#pragma unroll
                for (int nt = 0; nt < 8; nt++) {
                    const int cn = wn0 + nt * 8 + l4;
                    const unsigned int b0 = Bs[cn * LDS_S + k8 + lm];
                    const unsigned int b1 = Bs[cn * LDS_S + k8 + lm + 4];
#pragma unroll
                    for (int mt = 0; mt < 2; mt++) {
                        asm volatile(
                            "mma.sync.aligned.m16n8k8.row.col.f32.tf32.tf32.f32 "
                            "{%0,%1,%2,%3}, {%4,%5,%6,%7}, {%8,%9}, {%0,%1,%2,%3};"
                            : "+f"(acc[mt][nt][0]), "+f"(acc[mt][nt][1]),
                              "+f"(acc[mt][nt][2]), "+f"(acc[mt][nt][3])
                            : "r"(af[mt][0]), "r"(af[mt][1]), "r"(af[mt][2]), "r"(af[mt][3]),
                              "r"(b0), "r"(b1));
                    }
                }
            }
        }

        // epilogue: atomic accumulate (+bias once per element)
#pragma unroll
        for (int mt = 0; mt < 2; mt++) {
            const int rr0 = bm + wm0 + mt * 16 + l4;
            const int rr1 = rr0 + 8;
#pragma unroll
            for (int nt = 0; nt < 8; nt++) {
                const int c = bn + wn0 + nt * 8 + lm * 2;
                const float b0 = bias[c], b1 = bias[c + 1];
                if (rr0 < M) red2(out + (size_t)rr0 * H + c,
                                  acc[mt][nt][0] + b0, acc[mt][nt][1] + b1);
                if (rr1 < M) red2(out + (size_t)rr1 * H + c,
                                  acc[mt][nt][2] + b0, acc[mt][nt][3] + b1);
            }
        }
    } else {
        // ================= edge part: coalesced quad-per-base =================
        __shared__ int is64;
        if (tid == 0) {
            const int* s = (const int*)srcv;
            int orv = 0;
#pragma unroll
            for (int j = 0; j < 32; j++) orv |= s[2 * j + 1];
            is64 = (orv == 0) ? 1 : 0;
        }
        __syncthreads();

        const int e = (int)(bid - g) * EPB + wid;
        if (e >= E) return;

        long long s, d, t;
        if (is64) {
            s = ((const long long*)srcv)[e];
            d = ((const long long*)dstv)[e];
            t = ((const long long*)etv)[e];
        } else {
            s = ((const int*)srcv)[e];
            d = ((const int*)dstv)[e];
            t = ((const int*)etv)[e];
        }
        const float nr = norm[e];

        const float4* wbase = (const float4*)(wt + (size_t)t * 2048) + lane;
        const float*  hbase = A + (size_t)s * H + lane;
        float* obase        = out + (size_t)d * H + (lane >> 2) * 4;
        const bool writer   = (lane & 3) == 0;

#pragma unroll 4
        for (int p = 0; p < 16; p++) {
            const float4 w = wbase[p * 32];
            const float hv = hbase[p * 32];
            float4 m = make_float4(hv * w.x, hv * w.y, hv * w.z, hv * w.w);
            m.x += __shfl_xor_sync(0xFFFFFFFFu, m.x, 1);
            m.y += __shfl_xor_sync(0xFFFFFFFFu, m.y, 1);
            m.z += __shfl_xor_sync(0xFFFFFFFFu, m.z, 1);
            m.w += __shfl_xor_sync(0xFFFFFFFFu, m.w, 1);
            m.x += __shfl_xor_sync(0xFFFFFFFFu, m.x, 2);
            m.y += __shfl_xor_sync(0xFFFFFFFFu, m.y, 2);
            m.z += __shfl_xor_sync(0xFFFFFFFFu, m.z, 2);
            m.w += __shfl_xor_sync(0xFFFFFFFFu, m.w, 2);
            if (writer) {
                m.x *= nr; m.y *= nr; m.z *= nr; m.w *= nr;
                red4(obase + p * 32, m);
            }
        }
    }
}

// ---------------- launch ----------------
extern "C" void kernel_launch(void* const* d_in, const int* in_sizes, int n_in,
                              void* d_out, int out_size)
{
    // 0=node_ids (arange, unused), 1=src, 2=dst, 3=etypes, 4=norm,
    // 5=emb, 6=weight, 7=loop_weight, 8=bias
    const float* norm = (const float*)d_in[4];
    const float* emb  = (const float*)d_in[5];
    const float* wt   = (const float*)d_in[6];
    const float* lw   = (const float*)d_in[7];
    const float* bias = (const float*)d_in[8];
    float* out = (float*)d_out;

    const int M = in_sizes[5] / H;
    const int E = in_sizes[1];

    transpose512<<<dim3(16, 16), dim3(32, 8)>>>(lw);

    const int n4 = M * (H / 4);
    cvtA_kernel<<<(n4 + 255) / 256, 256>>>(emb, n4);

    cudaMemsetAsync(d_out, 0, (size_t)out_size * sizeof(float));

    static int smem_set = 0;
    if (!smem_set) {
        cudaFuncSetAttribute(fused_kernel,
                             cudaFuncAttributeMaxDynamicSharedMemorySize, SMEM_DYN);
        smem_set = 1;
    }

    const int GB  = ((M + 127) / 128) * 4;   // 128x128 gemm tiles
    const int EB  = (E + EPB - 1) / EPB;     // edge blocks
    const int TOT = GB + EB;
    fused_kernel<<<TOT, 256, SMEM_DYN>>>(emb, bias, d_in[1], d_in[2], d_in[3],
                                         norm, wt, out, M, E, GB, TOT);
}

// round 11
// speedup vs baseline: 1.4819x; 1.4819x over previous
#include <cuda_runtime.h>
#include <cstdint>

#define H      512
#define EPB    8

// ---------------- scratch: transposed loop weight, tf32-rounded ----------------
__device__ unsigned int g_Bt[H * H];   // Bt[n][k] = tf32(lw[k][n])

__device__ __forceinline__ unsigned int f2tf32(float f) {
    unsigned int u;
    asm("cvt.rna.tf32.f32 %0, %1;" : "=r"(u) : "f"(f));
    return u;
}
__device__ __forceinline__ uint32_t smem_u32(const void* p) {
    uint32_t a;
    asm("{ .reg .u64 t; cvta.to.shared.u64 t, %1; cvt.u32.u64 %0, t; }" : "=r"(a) : "l"(p));
    return a;
}
__device__ __forceinline__ void cp_async16(void* sptr, const void* gptr) {
    asm volatile("cp.async.cg.shared.global [%0], [%1], 16;"
                 :: "r"(smem_u32(sptr)), "l"(gptr));
}
// zero-fill variant: src-size = 0 or 16
__device__ __forceinline__ void cp_async16_p(void* sptr, const void* gptr, bool valid) {
    int sz = valid ? 16 : 0;
    asm volatile("cp.async.cg.shared.global [%0], [%1], 16, %2;"
                 :: "r"(smem_u32(sptr)), "l"(gptr), "r"(sz));
}
__device__ __forceinline__ void red4(float* p, float4 v) {
    asm volatile("red.global.add.v4.f32 [%0], {%1, %2, %3, %4};"
                 :: "l"(p), "f"(v.x), "f"(v.y), "f"(v.z), "f"(v.w) : "memory");
}

// ---------------- transpose 512x512 + tf32 round ----------------
__global__ void transpose512(const float* __restrict__ lw) {
    __shared__ float t[32][33];
    const int bx = blockIdx.x * 32, by = blockIdx.y * 32;
#pragma unroll
    for (int j = 0; j < 4; j++)
        t[threadIdx.y + 8 * j][threadIdx.x] =
            lw[(by + threadIdx.y + 8 * j) * H + bx + threadIdx.x];
    __syncthreads();
#pragma unroll
    for (int j = 0; j < 4; j++)
        g_Bt[(bx + threadIdx.y + 8 * j) * H + by + threadIdx.x] =
            f2tf32(t[threadIdx.x][threadIdx.y + 8 * j]);
}

// ---------------- GEMM kernel: out = emb @ lw + bias (plain stores) ----------------
// 128x128 tile, warp tile 32x64, 3-stage cp.async pipeline.
// A streamed raw fp32 (mma.tf32 truncates implicitly); B pre-rounded RNA.
#define BK      16
#define LDS_S   20
#define STG_U   (2 * 128 * LDS_S)      // uints per stage (A then B)
#define A_OFF   0
#define B_OFF   (128 * LDS_S)
#define SMEM_DYN (3 * STG_U * 4)       // 61440 bytes

__global__ __launch_bounds__(256)
void gemm_kernel(const float* __restrict__ A, const float* __restrict__ bias,
                 float* __restrict__ out, int M)
{
    extern __shared__ unsigned int smemu[];

    const int tid  = threadIdx.x;
    const int wid  = tid >> 5;
    const int lane = tid & 31;
    const int l4   = lane >> 2;
    const int lm   = lane & 3;
    const int bm   = (blockIdx.x >> 2) * 128;
    const int bn   = (blockIdx.x & 3) * 128;
    const int wm0  = (wid & 3) * 32;
    const int wn0  = (wid >> 2) * 64;

    float acc[2][8][4];
#pragma unroll
    for (int i = 0; i < 2; i++)
#pragma unroll
        for (int j = 0; j < 8; j++)
#pragma unroll
            for (int q = 0; q < 4; q++) acc[i][j][q] = 0.f;

    // cp.async mapping: 2 A-rows + 2 B-rows per thread
    const int r0 = tid >> 2;            // 0..63
    const int r1 = (tid + 256) >> 2;    // 64..127
    const int kq = tid & 3;
    const bool v0 = (bm + r0) < M;
    const bool v1 = (bm + r1) < M;

    auto issue_stage = [&](int kt, int s) {
        unsigned int* As = smemu + s * STG_U + A_OFF;
        unsigned int* Bs = smemu + s * STG_U + B_OFF;
        cp_async16_p(&As[r0 * LDS_S + kq * 4],
                     A + (size_t)(bm + r0) * H + kt + kq * 4, v0);
        cp_async16_p(&As[r1 * LDS_S + kq * 4],
                     A + (size_t)(bm + r1) * H + kt + kq * 4, v1);
        cp_async16(&Bs[r0 * LDS_S + kq * 4],
                   g_Bt + (size_t)(bn + r0) * H + kt + kq * 4);
        cp_async16(&Bs[r1 * LDS_S + kq * 4],
                   g_Bt + (size_t)(bn + r1) * H + kt + kq * 4);
    };

    const int NK = H / BK;   // 32
    issue_stage(0, 0);
    asm volatile("cp.async.commit_group;");
    issue_stage(BK, 1);
    asm volatile("cp.async.commit_group;");

    for (int kt = 0; kt < NK; kt++) {
        asm volatile("cp.async.wait_group 1;");
        __syncthreads();

        if (kt + 2 < NK) issue_stage((kt + 2) * BK, (kt + 2) % 3);
        asm volatile("cp.async.commit_group;");

        const unsigned int* As = smemu + (kt % 3) * STG_U + A_OFF;
        const unsigned int* Bs = smemu + (kt % 3) * STG_U + B_OFF;
#pragma unroll
        for (int ks = 0; ks < 2; ks++) {
            const int k8 = ks * 8;
            unsigned int af[2][4];
#pragma unroll
            for (int mt = 0; mt < 2; mt++) {
                const int rm = wm0 + mt * 16 + l4;
                af[mt][0] = As[rm * LDS_S + k8 + lm];
                af[mt][1] = As[(rm + 8) * LDS_S + k8 + lm];
                af[mt][2] = As[rm * LDS_S + k8 + lm + 4];
                af[mt][3] = As[(rm + 8) * LDS_S + k8 + lm + 4];
            }
#pragma unroll
            for (int nt = 0; nt < 8; nt++) {
                const int cn = wn0 + nt * 8 + l4;
                const unsigned int b0 = Bs[cn * LDS_S + k8 + lm];
                const unsigned int b1 = Bs[cn * LDS_S + k8 + lm + 4];
#pragma unroll
                for (int mt = 0; mt < 2; mt++) {
                    asm volatile(
                        "mma.sync.aligned.m16n8k8.row.col.f32.tf32.tf32.f32 "
                        "{%0,%1,%2,%3}, {%4,%5,%6,%7}, {%8,%9}, {%0,%1,%2,%3};"
                        : "+f"(acc[mt][nt][0]), "+f"(acc[mt][nt][1]),
                          "+f"(acc[mt][nt][2]), "+f"(acc[mt][nt][3])
                        : "r"(af[mt][0]), "r"(af[mt][1]), "r"(af[mt][2]), "r"(af[mt][3]),
                          "r"(b0), "r"(b1));
                }
            }
        }
    }

    // epilogue: bias + plain stores (covers every out element exactly once)
#pragma unroll
    for (int mt = 0; mt < 2; mt++) {
        const int rr0 = bm + wm0 + mt * 16 + l4;
        const int rr1 = rr0 + 8;
#pragma unroll
        for (int nt = 0; nt < 8; nt++) {
            const int c = bn + wn0 + nt * 8 + lm * 2;
            const float b0 = bias[c], b1 = bias[c + 1];
            if (rr0 < M)
                *(float2*)(out + (size_t)rr0 * H + c) =
                    make_float2(acc[mt][nt][0] + b0, acc[mt][nt][1] + b1);
            if (rr1 < M)
                *(float2*)(out + (size_t)rr1 * H + c) =
                    make_float2(acc[mt][nt][2] + b0, acc[mt][nt][3] + b1);
        }
    }
}

// ---------------- Edge kernel: coalesced quad-per-base ----------------
__global__ __launch_bounds__(256)
void edge_kernel(const void* __restrict__ srcv, const void* __restrict__ dstv,
                 const void* __restrict__ etv, const float* __restrict__ norm,
                 const float* __restrict__ emb, const float* __restrict__ wt,
                 float* __restrict__ out, int E)
{
    __shared__ int is64;
    if (threadIdx.x == 0) {
        const int* s = (const int*)srcv;
        int orv = 0;
#pragma unroll
        for (int j = 0; j < 32; j++) orv |= s[2 * j + 1];
        is64 = (orv == 0) ? 1 : 0;
    }
    __syncthreads();

    const int wid  = threadIdx.x >> 5;
    const int lane = threadIdx.x & 31;
    const int e    = blockIdx.x * EPB + wid;
    if (e >= E) return;

    long long s, d, t;
    if (is64) {
        s = ((const long long*)srcv)[e];
        d = ((const long long*)dstv)[e];
        t = ((const long long*)etv)[e];
    } else {
        s = ((const int*)srcv)[e];
        d = ((const int*)dstv)[e];
        t = ((const int*)etv)[e];
    }
    const float nr = norm[e];

    // lane = (g=lane>>2, i=lane&3); pass p covers bases p*8..p*8+7.
    const float4* wbase = (const float4*)(wt + (size_t)t * 2048) + lane;
    const float*  hbase = emb + (size_t)s * H + lane;
    float* obase        = out + (size_t)d * H + (lane >> 2) * 4;
    const bool writer   = (lane & 3) == 0;

#pragma unroll 4
    for (int p = 0; p < 16; p++) {
        const float4 w = wbase[p * 32];      // warp-contiguous 512B
        const float hv = hbase[p * 32];      // warp-contiguous 128B
        float4 m = make_float4(hv * w.x, hv * w.y, hv * w.z, hv * w.w);
        m.x += __shfl_xor_sync(0xFFFFFFFFu, m.x, 1);
        m.y += __shfl_xor_sync(0xFFFFFFFFu, m.y, 1);
        m.z += __shfl_xor_sync(0xFFFFFFFFu, m.z, 1);
        m.w += __shfl_xor_sync(0xFFFFFFFFu, m.w, 1);
        m.x += __shfl_xor_sync(0xFFFFFFFFu, m.x, 2);
        m.y += __shfl_xor_sync(0xFFFFFFFFu, m.y, 2);
        m.z += __shfl_xor_sync(0xFFFFFFFFu, m.z, 2);
        m.w += __shfl_xor_sync(0xFFFFFFFFu, m.w, 2);
        if (writer) {
            m.x *= nr; m.y *= nr; m.z *= nr; m.w *= nr;
            red4(obase + p * 32, m);         // 8 lanes, contiguous 128B
        }
    }
}

// ---------------- launch ----------------
extern "C" void kernel_launch(void* const* d_in, const int* in_sizes, int n_in,
                              void* d_out, int out_size)
{
    // 0=node_ids (arange, unused), 1=src, 2=dst, 3=etypes, 4=norm,
    // 5=emb, 6=weight, 7=loop_weight, 8=bias
    const float* norm = (const float*)d_in[4];
    const float* emb  = (const float*)d_in[5];
    const float* wt   = (const float*)d_in[6];
    const float* lw   = (const float*)d_in[7];
    const float* bias = (const float*)d_in[8];
    float* out = (float*)d_out;

    const int M = in_sizes[5] / H;
    const int E = in_sizes[1];

    transpose512<<<dim3(16, 16), dim3(32, 8)>>>(lw);

    static int smem_set = 0;
    if (!smem_set) {
        cudaFuncSetAttribute(gemm_kernel,
                             cudaFuncAttributeMaxDynamicSharedMemorySize, SMEM_DYN);
        smem_set = 1;
    }

    const int GB = ((M + 127) / 128) * 4;    // 128x128 tiles
    gemm_kernel<<<GB, 256, SMEM_DYN>>>(emb, bias, out, M);

    edge_kernel<<<(E + EPB - 1) / EPB, 256>>>(d_in[1], d_in[2], d_in[3],
                                              norm, emb, wt, out, E);
}

// round 12
// speedup vs baseline: 1.6681x; 1.1257x over previous
#include <cuda_runtime.h>
#include <cstdint>

#define H      512
#define EPB    8

// ---------------- scratch: transposed loop weight, tf32-rounded ----------------
__device__ unsigned int g_Bt[H * H];   // Bt[n][k] = tf32(lw[k][n])

__device__ __forceinline__ unsigned int f2tf32(float f) {
    unsigned int u;
    asm("cvt.rna.tf32.f32 %0, %1;" : "=r"(u) : "f"(f));
    return u;
}
__device__ __forceinline__ uint32_t smem_u32(const void* p) {
    uint32_t a;
    asm("{ .reg .u64 t; cvta.to.shared.u64 t, %1; cvt.u32.u64 %0, t; }" : "=r"(a) : "l"(p));
    return a;
}
__device__ __forceinline__ void cp_async16(void* sptr, const void* gptr) {
    asm volatile("cp.async.cg.shared.global [%0], [%1], 16;"
                 :: "r"(smem_u32(sptr)), "l"(gptr));
}
// zero-fill variant: src-size = 0 or 16
__device__ __forceinline__ void cp_async16_p(void* sptr, const void* gptr, bool valid) {
    int sz = valid ? 16 : 0;
    asm volatile("cp.async.cg.shared.global [%0], [%1], 16, %2;"
                 :: "r"(smem_u32(sptr)), "l"(gptr), "r"(sz));
}
__device__ __forceinline__ void red4(float* p, float4 v) {
    asm volatile("red.global.add.v4.f32 [%0], {%1, %2, %3, %4};"
                 :: "l"(p), "f"(v.x), "f"(v.y), "f"(v.z), "f"(v.w) : "memory");
}

// ---------------- transpose 512x512 + tf32 round ----------------
__global__ void transpose512(const float* __restrict__ lw) {
    __shared__ float t[32][33];
    const int bx = blockIdx.x * 32, by = blockIdx.y * 32;
#pragma unroll
    for (int j = 0; j < 4; j++)
        t[threadIdx.y + 8 * j][threadIdx.x] =
            lw[(by + threadIdx.y + 8 * j) * H + bx + threadIdx.x];
    __syncthreads();
#pragma unroll
    for (int j = 0; j < 4; j++)
        g_Bt[(bx + threadIdx.y + 8 * j) * H + by + threadIdx.x] =
            f2tf32(t[threadIdx.x][threadIdx.y + 8 * j]);
}

// ---------------- GEMM kernel: out = emb @ lw + bias ----------------
// 128x128 tile, warp tile 32x64, BK=32, 2-stage cp.async double buffer.
// A streamed raw fp32 (mma.tf32 truncates implicitly); B pre-rounded RNA.
#define BK      32
#define LDS_S   36                      // 32 data + 4 pad uints per row
#define STG_U   (2 * 128 * LDS_S)       // uints per stage (A then B)
#define A_OFF   0
#define B_OFF   (128 * LDS_S)
#define SMEM_DYN (2 * STG_U * 4)        // 73728 bytes

__global__ __launch_bounds__(256, 2)
void gemm_kernel(const float* __restrict__ A, const float* __restrict__ bias,
                 float* __restrict__ out, int M)
{
    extern __shared__ unsigned int smemu[];

    const int tid  = threadIdx.x;
    const int wid  = tid >> 5;
    const int lane = tid & 31;
    const int l4   = lane >> 2;
    const int lm   = lane & 3;
    const int bm   = (blockIdx.x >> 2) * 128;
    const int bn   = (blockIdx.x & 3) * 128;
    const int wm0  = (wid & 3) * 32;
    const int wn0  = (wid >> 2) * 64;

    float acc[2][8][4];
#pragma unroll
    for (int i = 0; i < 2; i++)
#pragma unroll
        for (int j = 0; j < 8; j++)
#pragma unroll
            for (int q = 0; q < 4; q++) acc[i][j][q] = 0.f;

    // cp.async mapping: per stage, A = 128 rows x 8 chunks (16B), B same.
    // Thread t: A chunks idx = t + i*256 (i=0..3), B chunks same.
    auto issue_stage = [&](int kt, int s) {
        unsigned int* As = smemu + s * STG_U + A_OFF;
        unsigned int* Bs = smemu + s * STG_U + B_OFF;
#pragma unroll
        for (int i = 0; i < 4; i++) {
            const int idx = tid + i * 256;
            const int row = idx >> 3;
            const int kq  = idx & 7;
            cp_async16_p(&As[row * LDS_S + kq * 4],
                         A + (size_t)(bm + row) * H + kt + kq * 4, (bm + row) < M);
            cp_async16(&Bs[row * LDS_S + kq * 4],
                       g_Bt + (size_t)(bn + row) * H + kt + kq * 4);
        }
    };

    const int NK = H / BK;   // 16
    issue_stage(0, 0);
    asm volatile("cp.async.commit_group;");

    for (int kt = 0; kt < NK; kt++) {
        if (kt + 1 < NK) {
            issue_stage((kt + 1) * BK, (kt + 1) & 1);
            asm volatile("cp.async.commit_group;");
            asm volatile("cp.async.wait_group 1;");
        } else {
            asm volatile("cp.async.wait_group 0;");
        }
        __syncthreads();

        const unsigned int* As = smemu + (kt & 1) * STG_U + A_OFF;
        const unsigned int* Bs = smemu + (kt & 1) * STG_U + B_OFF;
#pragma unroll
        for (int ks = 0; ks < 4; ks++) {
            const int k8 = ks * 8;
            unsigned int af[2][4];
#pragma unroll
            for (int mt = 0; mt < 2; mt++) {
                const int rm = wm0 + mt * 16 + l4;
                af[mt][0] = As[rm * LDS_S + k8 + lm];
                af[mt][1] = As[(rm + 8) * LDS_S + k8 + lm];
                af[mt][2] = As[rm * LDS_S + k8 + lm + 4];
                af[mt][3] = As[(rm + 8) * LDS_S + k8 + lm + 4];
            }
#pragma unroll
            for (int nt = 0; nt < 8; nt++) {
                const int cn = wn0 + nt * 8 + l4;
                const unsigned int b0 = Bs[cn * LDS_S + k8 + lm];
                const unsigned int b1 = Bs[cn * LDS_S + k8 + lm + 4];
#pragma unroll
                for (int mt = 0; mt < 2; mt++) {
                    asm volatile(
                        "mma.sync.aligned.m16n8k8.row.col.f32.tf32.tf32.f32 "
                        "{%0,%1,%2,%3}, {%4,%5,%6,%7}, {%8,%9}, {%0,%1,%2,%3};"
                        : "+f"(acc[mt][nt][0]), "+f"(acc[mt][nt][1]),
                          "+f"(acc[mt][nt][2]), "+f"(acc[mt][nt][3])
                        : "r"(af[mt][0]), "r"(af[mt][1]), "r"(af[mt][2]), "r"(af[mt][3]),
                          "r"(b0), "r"(b1));
                }
            }
        }
        __syncthreads();
    }

    // epilogue: bias + plain stores
#pragma unroll
    for (int mt = 0; mt < 2; mt++) {
        const int rr0 = bm + wm0 + mt * 16 + l4;
        const int rr1 = rr0 + 8;
#pragma unroll
        for (int nt = 0; nt < 8; nt++) {
            const int c = bn + wn0 + nt * 8 + lm * 2;
            const float b0 = bias[c], b1 = bias[c + 1];
            if (rr0 < M)
                *(float2*)(out + (size_t)rr0 * H + c) =
                    make_float2(acc[mt][nt][0] + b0, acc[mt][nt][1] + b1);
            if (rr1 < M)
                *(float2*)(out + (size_t)rr1 * H + c) =
                    make_float2(acc[mt][nt][2] + b0, acc[mt][nt][3] + b1);
        }
    }
}

// ---------------- Edge kernel: coalesced quad-per-base ----------------
__global__ __launch_bounds__(256)
void edge_kernel(const void* __restrict__ srcv, const void* __restrict__ dstv,
                 const void* __restrict__ etv, const float* __restrict__ norm,
                 const float* __restrict__ emb, const float* __restrict__ wt,
                 float* __restrict__ out, int E)
{
    __shared__ int is64;
    if (threadIdx.x == 0) {
        const int* s = (const int*)srcv;
        int orv = 0;
#pragma unroll
        for (int j = 0; j < 32; j++) orv |= s[2 * j + 1];
        is64 = (orv == 0) ? 1 : 0;
    }
    __syncthreads();

    const int wid  = threadIdx.x >> 5;
    const int lane = threadIdx.x & 31;
    const int e    = blockIdx.x * EPB + wid;
    if (e >= E) return;

    long long s, d, t;
    if (is64) {
        s = ((const long long*)srcv)[e];
        d = ((const long long*)dstv)[e];
        t = ((const long long*)etv)[e];
    } else {
        s = ((const int*)srcv)[e];
        d = ((const int*)dstv)[e];
        t = ((const int*)etv)[e];
    }
    const float nr = norm[e];

    const float4* wbase = (const float4*)(wt + (size_t)t * 2048) + lane;
    const float*  hbase = emb + (size_t)s * H + lane;
    float* obase        = out + (size_t)d * H + (lane >> 2) * 4;
    const bool writer   = (lane & 3) == 0;

#pragma unroll 4
    for (int p = 0; p < 16; p++) {
        const float4 w = wbase[p * 32];      // warp-contiguous 512B
        const float hv = hbase[p * 32];      // warp-contiguous 128B
        float4 m = make_float4(hv * w.x, hv * w.y, hv * w.z, hv * w.w);
        m.x += __shfl_xor_sync(0xFFFFFFFFu, m.x, 1);
        m.y += __shfl_xor_sync(0xFFFFFFFFu, m.y, 1);
        m.z += __shfl_xor_sync(0xFFFFFFFFu, m.z, 1);
        m.w += __shfl_xor_sync(0xFFFFFFFFu, m.w, 1);
        m.x += __shfl_xor_sync(0xFFFFFFFFu, m.x, 2);
        m.y += __shfl_xor_sync(0xFFFFFFFFu, m.y, 2);
        m.z += __shfl_xor_sync(0xFFFFFFFFu, m.z, 2);
        m.w += __shfl_xor_sync(0xFFFFFFFFu, m.w, 2);
        if (writer) {
            m.x *= nr; m.y *= nr; m.z *= nr; m.w *= nr;
            red4(obase + p * 32, m);         // 8 lanes, contiguous 128B
        }
    }
}

// ---------------- launch ----------------
extern "C" void kernel_launch(void* const* d_in, const int* in_sizes, int n_in,
                              void* d_out, int out_size)
{
    // 0=node_ids (arange, unused), 1=src, 2=dst, 3=etypes, 4=norm,
    // 5=emb, 6=weight, 7=loop_weight, 8=bias
    const float* norm = (const float*)d_in[4];
    const float* emb  = (const float*)d_in[5];
    const float* wt   = (const float*)d_in[6];
    const float* lw   = (const float*)d_in[7];
    const float* bias = (const float*)d_in[8];
    float* out = (float*)d_out;

    const int M = in_sizes[5] / H;
    const int E = in_sizes[1];

    transpose512<<<dim3(16, 16), dim3(32, 8)>>>(lw);

    static int smem_set = 0;
    if (!smem_set) {
        cudaFuncSetAttribute(gemm_kernel,
                             cudaFuncAttributeMaxDynamicSharedMemorySize, SMEM_DYN);
        smem_set = 1;
    }

    const int GB = ((M + 127) / 128) * 4;    // 128x128 tiles
    gemm_kernel<<<GB, 256, SMEM_DYN>>>(emb, bias, out, M);

    edge_kernel<<<(E + EPB - 1) / EPB, 256>>>(d_in[1], d_in[2], d_in[3],
                                              norm, emb, wt, out, E);
}